// round 1
// baseline (speedup 1.0000x reference)
#include <cuda_runtime.h>
#include <math.h>

// Sliding-window attention, B=1, H=16, S=4096, D=64, half-window 256, fp32.
// Round 1: SIMT flash-attention baseline. One CTA = (head, 64-query tile).
// 256 threads as 16(ty: query groups of 4) x 16(tx: key/dim groups of 4).

#define NH    16
#define SEQ   4096
#define HD    64
#define WHALF 256
#define BQ    64
#define BK    64
#define PAD   68            // floats per smem row: 16B-aligned, low-conflict

#define SMEM_FLOATS (4 * 64 * PAD)          // Qs + Ks + Vs + Ps
#define SMEM_BYTES  (SMEM_FLOATS * 4)       // 69632 B

__global__ __launch_bounds__(256, 2)
void swa_kernel(const float* __restrict__ gq, const float* __restrict__ gk,
                const float* __restrict__ gv, float* __restrict__ gout)
{
    extern __shared__ float sm[];
    float* Qs = sm;              // [HD][PAD]  transposed: Qs[d][q]
    float* Ks = Qs + 64 * PAD;   // [HD][PAD]  transposed: Ks[d][k]
    float* Vs = Ks + 64 * PAD;   // [BK][PAD]  natural:    Vs[k][d]
    float* Ps = Vs + 64 * PAD;   // [BQ][PAD]  natural:    Ps[q][k]

    const int q0  = blockIdx.x * BQ;
    const int h   = blockIdx.y;
    const int tid = threadIdx.x;
    const int ty  = tid >> 4;    // 0..15 : query group (4 queries)
    const int tx  = tid & 15;    // 0..15 : key/dim group (4 each)

    const float* qh = gq + (size_t)h * SEQ * HD;
    const float* kh = gk + (size_t)h * SEQ * HD;
    const float* vh = gv + (size_t)h * SEQ * HD;
    float*       oh = gout + (size_t)h * SEQ * HD;

    // ---- load Q tile, transposed into Qs[d][q] ----
    {
        const int r  = tid >> 2;   // 0..63 row (query)
        const int c4 = tid & 3;    // float4-column subgroup
        #pragma unroll
        for (int rep = 0; rep < 4; rep++) {
            const int cc = c4 + rep * 4;   // float4 col 0..15
            float4 t = *(const float4*)(qh + (size_t)(q0 + r) * HD + cc * 4);
            Qs[(cc * 4 + 0) * PAD + r] = t.x;
            Qs[(cc * 4 + 1) * PAD + r] = t.y;
            Qs[(cc * 4 + 2) * PAD + r] = t.z;
            Qs[(cc * 4 + 3) * PAD + r] = t.w;
        }
    }

    float acc[4][4];
    #pragma unroll
    for (int i = 0; i < 4; i++)
        #pragma unroll
        for (int j = 0; j < 4; j++) acc[i][j] = 0.f;
    float mi[4] = {-1e30f, -1e30f, -1e30f, -1e30f};
    float li[4] = {0.f, 0.f, 0.f, 0.f};

    const int   kstart = (q0 - WHALF) > 0 ? (q0 - WHALF) : 0;      // multiple of 64
    const int   kend   = (q0 + BQ + WHALF) < SEQ ? (q0 + BQ + WHALF) : SEQ;
    const float scale  = 0.125f;   // 1/sqrt(64)

    __syncthreads();   // Qs ready

    for (int k0 = kstart; k0 < kend; k0 += BK) {
        __syncthreads();   // protect Ks/Vs/Ps from previous iteration's readers

        // ---- load K tile (transposed) + V tile (natural) ----
        {
            const int r  = tid >> 2;
            const int c4 = tid & 3;
            #pragma unroll
            for (int rep = 0; rep < 4; rep++) {
                const int cc = c4 + rep * 4;
                float4 t = *(const float4*)(kh + (size_t)(k0 + r) * HD + cc * 4);
                Ks[(cc * 4 + 0) * PAD + r] = t.x;
                Ks[(cc * 4 + 1) * PAD + r] = t.y;
                Ks[(cc * 4 + 2) * PAD + r] = t.z;
                Ks[(cc * 4 + 3) * PAD + r] = t.w;
                float4 tv = *(const float4*)(vh + (size_t)(k0 + r) * HD + cc * 4);
                *(float4*)(Vs + r * PAD + cc * 4) = tv;
            }
        }
        __syncthreads();

        // ---- S = Q K^T (4x4 register tile per thread) ----
        float s[4][4];
        #pragma unroll
        for (int i = 0; i < 4; i++)
            #pragma unroll
            for (int j = 0; j < 4; j++) s[i][j] = 0.f;

        #pragma unroll 8
        for (int d = 0; d < HD; d++) {
            float4 a = *(const float4*)(Qs + d * PAD + ty * 4);
            float4 b = *(const float4*)(Ks + d * PAD + tx * 4);
            s[0][0] = fmaf(a.x, b.x, s[0][0]); s[0][1] = fmaf(a.x, b.y, s[0][1]);
            s[0][2] = fmaf(a.x, b.z, s[0][2]); s[0][3] = fmaf(a.x, b.w, s[0][3]);
            s[1][0] = fmaf(a.y, b.x, s[1][0]); s[1][1] = fmaf(a.y, b.y, s[1][1]);
            s[1][2] = fmaf(a.y, b.z, s[1][2]); s[1][3] = fmaf(a.y, b.w, s[1][3]);
            s[2][0] = fmaf(a.z, b.x, s[2][0]); s[2][1] = fmaf(a.z, b.y, s[2][1]);
            s[2][2] = fmaf(a.z, b.z, s[2][2]); s[2][3] = fmaf(a.z, b.w, s[2][3]);
            s[3][0] = fmaf(a.w, b.x, s[3][0]); s[3][1] = fmaf(a.w, b.y, s[3][1]);
            s[3][2] = fmaf(a.w, b.z, s[3][2]); s[3][3] = fmaf(a.w, b.w, s[3][3]);
        }

        // ---- scale + band mask ----
        #pragma unroll
        for (int i = 0; i < 4; i++) {
            const int qi = q0 + ty * 4 + i;
            #pragma unroll
            for (int j = 0; j < 4; j++) {
                const int kj = k0 + tx * 4 + j;
                const bool valid = (unsigned)(qi - kj + WHALF) <= (unsigned)(2 * WHALF);
                s[i][j] = valid ? s[i][j] * scale : -1e30f;
            }
        }

        // ---- online softmax (row reductions across the 16 tx lanes) ----
        #pragma unroll
        for (int i = 0; i < 4; i++) {
            float rm = fmaxf(fmaxf(s[i][0], s[i][1]), fmaxf(s[i][2], s[i][3]));
            rm = fmaxf(rm, __shfl_xor_sync(0xffffffffu, rm, 1));
            rm = fmaxf(rm, __shfl_xor_sync(0xffffffffu, rm, 2));
            rm = fmaxf(rm, __shfl_xor_sync(0xffffffffu, rm, 4));
            rm = fmaxf(rm, __shfl_xor_sync(0xffffffffu, rm, 8));
            const float mnew  = fmaxf(mi[i], rm);
            const float alpha = __expf(mi[i] - mnew);
            mi[i] = mnew;

            float rs = 0.f;
            #pragma unroll
            for (int j = 0; j < 4; j++) {
                s[i][j] = __expf(s[i][j] - mnew);
                rs += s[i][j];
            }
            rs += __shfl_xor_sync(0xffffffffu, rs, 1);
            rs += __shfl_xor_sync(0xffffffffu, rs, 2);
            rs += __shfl_xor_sync(0xffffffffu, rs, 4);
            rs += __shfl_xor_sync(0xffffffffu, rs, 8);

            li[i] = li[i] * alpha + rs;
            #pragma unroll
            for (int j = 0; j < 4; j++) acc[i][j] *= alpha;

            *(float4*)(Ps + (ty * 4 + i) * PAD + tx * 4) =
                make_float4(s[i][0], s[i][1], s[i][2], s[i][3]);
        }
        __syncthreads();   // Ps ready

        // ---- O += P V (vectorized 4-wide over k) ----
        #pragma unroll 2
        for (int kk = 0; kk < BK; kk += 4) {
            float4 b0 = *(const float4*)(Vs + (kk + 0) * PAD + tx * 4);
            float4 b1 = *(const float4*)(Vs + (kk + 1) * PAD + tx * 4);
            float4 b2 = *(const float4*)(Vs + (kk + 2) * PAD + tx * 4);
            float4 b3 = *(const float4*)(Vs + (kk + 3) * PAD + tx * 4);
            #pragma unroll
            for (int i = 0; i < 4; i++) {
                float4 ai = *(const float4*)(Ps + (ty * 4 + i) * PAD + kk);
                acc[i][0] = fmaf(ai.x, b0.x, fmaf(ai.y, b1.x, fmaf(ai.z, b2.x, fmaf(ai.w, b3.x, acc[i][0]))));
                acc[i][1] = fmaf(ai.x, b0.y, fmaf(ai.y, b1.y, fmaf(ai.z, b2.y, fmaf(ai.w, b3.y, acc[i][1]))));
                acc[i][2] = fmaf(ai.x, b0.z, fmaf(ai.y, b1.z, fmaf(ai.z, b2.z, fmaf(ai.w, b3.z, acc[i][2]))));
                acc[i][3] = fmaf(ai.x, b0.w, fmaf(ai.y, b1.w, fmaf(ai.z, b2.w, fmaf(ai.w, b3.w, acc[i][3]))));
            }
        }
    }

    // ---- epilogue: normalize and store ----
    #pragma unroll
    for (int i = 0; i < 4; i++) {
        const float inv = 1.f / li[i];
        float4 o = make_float4(acc[i][0] * inv, acc[i][1] * inv,
                               acc[i][2] * inv, acc[i][3] * inv);
        *(float4*)(oh + (size_t)(q0 + ty * 4 + i) * HD + tx * 4) = o;
    }
}

extern "C" void kernel_launch(void* const* d_in, const int* in_sizes, int n_in,
                              void* d_out, int out_size)
{
    const float* q = (const float*)d_in[0];
    const float* k = (const float*)d_in[1];
    const float* v = (const float*)d_in[2];
    float* out = (float*)d_out;
    (void)in_sizes; (void)n_in; (void)out_size;

    cudaFuncSetAttribute(swa_kernel, cudaFuncAttributeMaxDynamicSharedMemorySize,
                         SMEM_BYTES);

    dim3 grid(SEQ / BQ, NH);
    swa_kernel<<<grid, 256, SMEM_BYTES>>>(q, k, v, out);
}

// round 5
// speedup vs baseline: 2.0743x; 2.0743x over previous
#include <cuda_runtime.h>
#include <cstdint>
#include <math.h>

// Sliding-window attention, B=1,H=16,S=4096,D=64, half-window 256, fp32 I/O.
// Round 5: resubmit of Round 4 (container infra flake — kernel audited clean).
// mma.sync (HMMA) TF32 flash attention; tcgen05 unavailable (target sm_100).
// CTA = 256 thr (8 warps), BQ=128, BK=64. Each warp owns 16 query rows.
// m16n8k8 tf32 fragments; softmax in C-layout registers; P via warp-private
// SMEM rows; O accumulated in registers with online-softmax rescale.

#define SEQ   4096
#define NH    16
#define HD    64
#define WHALF 256
#define BQ    128
#define BK    64
#define SCALE 0.125f
#define PAD   68                 // floats per smem row

// SMEM float offsets
#define K_OFF 0                  // Ks [64][PAD]  tf32
#define V_OFF (64 * PAD)         // Vs [64][PAD]  tf32
#define Q_OFF (128 * PAD)        // Qs [128][PAD] tf32
#define P_OFF (Q_OFF + 128 * PAD)// Ps [128][PAD] tf32
#define SMEM_FLOATS (P_OFF + 128 * PAD)
#define SMEM_BYTES  (SMEM_FLOATS * 4)   // 104448 B

static __device__ __forceinline__ uint32_t f32_tf32(float f) {
    uint32_t r; asm("cvt.rna.tf32.f32 %0, %1;" : "=r"(r) : "f"(f)); return r;
}
static __device__ __forceinline__ void mma_tf32(float* c, const uint32_t* a,
                                                uint32_t b0, uint32_t b1) {
    asm volatile(
        "mma.sync.aligned.m16n8k8.row.col.f32.tf32.tf32.f32 "
        "{%0,%1,%2,%3}, {%4,%5,%6,%7}, {%8,%9}, {%0,%1,%2,%3};"
        : "+f"(c[0]), "+f"(c[1]), "+f"(c[2]), "+f"(c[3])
        : "r"(a[0]), "r"(a[1]), "r"(a[2]), "r"(a[3]), "r"(b0), "r"(b1));
}
static __device__ __forceinline__ bool in_band(int qi, int kj) {
    return (unsigned)(qi - kj + WHALF) <= (unsigned)(2 * WHALF);
}

__global__ __launch_bounds__(256, 2)
void swa_mma_kernel(const float* __restrict__ gq, const float* __restrict__ gk,
                    const float* __restrict__ gv, float* __restrict__ gout)
{
    extern __shared__ float sm[];
    uint32_t* KsU = (uint32_t*)(sm + K_OFF);
    uint32_t* VsU = (uint32_t*)(sm + V_OFF);
    uint32_t* QsU = (uint32_t*)(sm + Q_OFF);
    uint32_t* PsU = (uint32_t*)(sm + P_OFF);

    const int tid   = threadIdx.x;
    const int warp  = tid >> 5;          // 0..7
    const int lane  = tid & 31;
    const int group = lane >> 2;         // 0..7
    const int qp    = lane & 3;          // 0..3

    const int q0 = blockIdx.x * BQ;
    const int h  = blockIdx.y;

    const float* qh = gq + (size_t)h * SEQ * HD;
    const float* kh = gk + (size_t)h * SEQ * HD;
    const float* vh = gv + (size_t)h * SEQ * HD;
    float*       oh = gout + (size_t)h * SEQ * HD;

    const int r0  = warp * 16 + group;   // local query row (first of pair)
    const int r1  = r0 + 8;
    const int qi0 = q0 + r0;
    const int qi1 = q0 + r1;

    // ---- stage Q tile into SMEM as tf32 ----
    for (int idx = tid; idx < BQ * 16; idx += 256) {
        const int row = idx >> 4, c = (idx & 15) * 4;
        float4 t = *(const float4*)(qh + (size_t)(q0 + row) * HD + c);
        uint4 u = make_uint4(f32_tf32(t.x), f32_tf32(t.y), f32_tf32(t.z), f32_tf32(t.w));
        *(uint4*)(QsU + row * PAD + c) = u;
    }

    float oacc[8][4];
    #pragma unroll
    for (int nt = 0; nt < 8; nt++)
        #pragma unroll
        for (int j = 0; j < 4; j++) oacc[nt][j] = 0.f;
    float mi0 = -1e30f, mi1 = -1e30f, li0 = 0.f, li1 = 0.f;

    const int kstart = (q0 - WHALF) > 0 ? (q0 - WHALF) : 0;
    const int kend   = (q0 + BQ + WHALF) < SEQ ? (q0 + BQ + WHALF) : SEQ;

    for (int k0 = kstart; k0 < kend; k0 += BK) {
        __syncthreads();   // prior tile's readers done (Ks/Vs); Q staging done (1st iter)

        // ---- load K, V tiles as tf32 ----
        for (int idx = tid; idx < BK * 16; idx += 256) {
            const int row = idx >> 4, c = (idx & 15) * 4;
            float4 t = *(const float4*)(kh + (size_t)(k0 + row) * HD + c);
            *(uint4*)(KsU + row * PAD + c) =
                make_uint4(f32_tf32(t.x), f32_tf32(t.y), f32_tf32(t.z), f32_tf32(t.w));
            float4 tv = *(const float4*)(vh + (size_t)(k0 + row) * HD + c);
            *(uint4*)(VsU + row * PAD + c) =
                make_uint4(f32_tf32(tv.x), f32_tf32(tv.y), f32_tf32(tv.z), f32_tf32(tv.w));
        }
        __syncthreads();

        // ---- S = Q K^T : 8 d-chunks x 8 kv-tiles of m16n8k8 ----
        float sacc[8][4];
        #pragma unroll
        for (int nt = 0; nt < 8; nt++)
            #pragma unroll
            for (int j = 0; j < 4; j++) sacc[nt][j] = 0.f;

        #pragma unroll
        for (int kc = 0; kc < 8; kc++) {
            const int d0 = kc * 8;
            uint32_t aQ[4];
            aQ[0] = QsU[r0 * PAD + d0 + qp];
            aQ[1] = QsU[r1 * PAD + d0 + qp];
            aQ[2] = QsU[r0 * PAD + d0 + qp + 4];
            aQ[3] = QsU[r1 * PAD + d0 + qp + 4];
            #pragma unroll
            for (int nt = 0; nt < 8; nt++) {
                const int kv = nt * 8 + group;
                uint32_t b0 = KsU[kv * PAD + d0 + qp];
                uint32_t b1 = KsU[kv * PAD + d0 + qp + 4];
                mma_tf32(sacc[nt], aQ, b0, b1);
            }
        }

        // ---- masked row max (C layout: rows r0/r1, cols 8nt+2qp,+1) ----
        float m0 = -1e30f, m1 = -1e30f;
        #pragma unroll
        for (int nt = 0; nt < 8; nt++) {
            const int kj = k0 + nt * 8 + 2 * qp;
            float x;
            x = sacc[nt][0] * SCALE; if (in_band(qi0, kj)     && x > m0) m0 = x;
            x = sacc[nt][1] * SCALE; if (in_band(qi0, kj + 1) && x > m0) m0 = x;
            x = sacc[nt][2] * SCALE; if (in_band(qi1, kj)     && x > m1) m1 = x;
            x = sacc[nt][3] * SCALE; if (in_band(qi1, kj + 1) && x > m1) m1 = x;
        }
        m0 = fmaxf(m0, __shfl_xor_sync(0xffffffffu, m0, 1));
        m0 = fmaxf(m0, __shfl_xor_sync(0xffffffffu, m0, 2));
        m1 = fmaxf(m1, __shfl_xor_sync(0xffffffffu, m1, 1));
        m1 = fmaxf(m1, __shfl_xor_sync(0xffffffffu, m1, 2));

        const float mn0 = fmaxf(mi0, m0), mn1 = fmaxf(mi1, m1);
        const float al0 = __expf(mi0 - mn0), al1 = __expf(mi1 - mn1);
        mi0 = mn0; mi1 = mn1;

        // ---- exp + mask, P -> warp-private SMEM rows (tf32) ----
        float rs0 = 0.f, rs1 = 0.f;
        #pragma unroll
        for (int nt = 0; nt < 8; nt++) {
            const int kj = k0 + nt * 8 + 2 * qp;
            const float p00 = in_band(qi0, kj)     ? __expf(sacc[nt][0] * SCALE - mn0) : 0.f;
            const float p01 = in_band(qi0, kj + 1) ? __expf(sacc[nt][1] * SCALE - mn0) : 0.f;
            const float p10 = in_band(qi1, kj)     ? __expf(sacc[nt][2] * SCALE - mn1) : 0.f;
            const float p11 = in_band(qi1, kj + 1) ? __expf(sacc[nt][3] * SCALE - mn1) : 0.f;
            rs0 += p00 + p01;
            rs1 += p10 + p11;
            *(uint2*)(PsU + r0 * PAD + nt * 8 + 2 * qp) = make_uint2(f32_tf32(p00), f32_tf32(p01));
            *(uint2*)(PsU + r1 * PAD + nt * 8 + 2 * qp) = make_uint2(f32_tf32(p10), f32_tf32(p11));
        }
        rs0 += __shfl_xor_sync(0xffffffffu, rs0, 1);
        rs0 += __shfl_xor_sync(0xffffffffu, rs0, 2);
        rs1 += __shfl_xor_sync(0xffffffffu, rs1, 1);
        rs1 += __shfl_xor_sync(0xffffffffu, rs1, 2);
        li0 = li0 * al0 + rs0;
        li1 = li1 * al1 + rs1;

        // ---- rescale O ----
        #pragma unroll
        for (int nt = 0; nt < 8; nt++) {
            oacc[nt][0] *= al0; oacc[nt][1] *= al0;
            oacc[nt][2] *= al1; oacc[nt][3] *= al1;
        }
        __syncwarp();   // P rows are warp-private: warp-level sync suffices

        // ---- O += P V : 8 kv-chunks x 8 d-tiles ----
        #pragma unroll
        for (int kc = 0; kc < 8; kc++) {
            const int kv0 = kc * 8;
            uint32_t aP[4];
            aP[0] = PsU[r0 * PAD + kv0 + qp];
            aP[1] = PsU[r1 * PAD + kv0 + qp];
            aP[2] = PsU[r0 * PAD + kv0 + qp + 4];
            aP[3] = PsU[r1 * PAD + kv0 + qp + 4];
            #pragma unroll
            for (int nt = 0; nt < 8; nt++) {
                const int d0 = nt * 8;
                uint32_t b0 = VsU[(kv0 + qp) * PAD + d0 + group];
                uint32_t b1 = VsU[(kv0 + qp + 4) * PAD + d0 + group];
                mma_tf32(oacc[nt], aP, b0, b1);
            }
        }
    }

    // ---- epilogue: normalize, store (C layout -> gmem float2) ----
    const float inv0 = 1.f / li0;
    const float inv1 = 1.f / li1;
    #pragma unroll
    for (int nt = 0; nt < 8; nt++) {
        const int c = nt * 8 + 2 * qp;
        *(float2*)(oh + (size_t)qi0 * HD + c) = make_float2(oacc[nt][0] * inv0, oacc[nt][1] * inv0);
        *(float2*)(oh + (size_t)qi1 * HD + c) = make_float2(oacc[nt][2] * inv1, oacc[nt][3] * inv1);
    }
}

extern "C" void kernel_launch(void* const* d_in, const int* in_sizes, int n_in,
                              void* d_out, int out_size)
{
    const float* q = (const float*)d_in[0];
    const float* k = (const float*)d_in[1];
    const float* v = (const float*)d_in[2];
    float* out = (float*)d_out;
    (void)in_sizes; (void)n_in; (void)out_size;

    cudaFuncSetAttribute(swa_mma_kernel, cudaFuncAttributeMaxDynamicSharedMemorySize,
                         SMEM_BYTES);
    dim3 grid(SEQ / BQ, NH);
    swa_mma_kernel<<<grid, 256, SMEM_BYTES>>>(q, k, v, out);
}

// round 6
// speedup vs baseline: 3.1599x; 1.5233x over previous
#include <cuda_runtime.h>
#include <cstdint>
#include <math.h>

// Sliding-window attention, B=1,H=16,S=4096,D=64, half-window 256, fp32 I/O.
// Round 6: fp16 m16n8k16 HMMA flash attention (R5 was LDS-bound at 2.5
// LDS/MMA; fp16 halves both LDS words and MMA count, Q-fragments hoisted to
// registers for the whole KV loop, Q/P smem aliased).
// CTA = 256 thr (8 warps), BQ=128, BK=64; warp owns 16 query rows.

#define SEQ   4096
#define NH    16
#define HD    64
#define WHALF 256
#define BQ    128
#define BK    64
#define SCALE 0.125f
#define PADH  72                  // halfwords per smem row (144 B)
#define ROWW  (PADH / 2)          // 36 uint32 words per row

// SMEM uint32-word offsets
#define K_OFF  0                  // Ks [64][ROWW]   K tile, f16 pairs (row-major d)
#define VT_OFF (64 * ROWW)        // Vt [64][ROWW]   V transposed: [d][kv]
#define P_OFF  (128 * ROWW)       // Qs/Ps aliased [128][ROWW]
#define SMEM_WORDS (P_OFF + 128 * ROWW)
#define SMEM_BYTES (SMEM_WORDS * 4)      // 36864 B

static __device__ __forceinline__ uint32_t pack_f16x2(float lo, float hi) {
    uint32_t r;
    asm("cvt.rn.f16x2.f32 %0, %1, %2;" : "=r"(r) : "f"(hi), "f"(lo));
    return r;
}
static __device__ __forceinline__ void mma_f16(float* c, const uint32_t* a,
                                               uint32_t b0, uint32_t b1) {
    asm volatile(
        "mma.sync.aligned.m16n8k16.row.col.f32.f16.f16.f32 "
        "{%0,%1,%2,%3}, {%4,%5,%6,%7}, {%8,%9}, {%0,%1,%2,%3};"
        : "+f"(c[0]), "+f"(c[1]), "+f"(c[2]), "+f"(c[3])
        : "r"(a[0]), "r"(a[1]), "r"(a[2]), "r"(a[3]), "r"(b0), "r"(b1));
}
static __device__ __forceinline__ bool in_band(int qi, int kj) {
    return (unsigned)(qi - kj + WHALF) <= (unsigned)(2 * WHALF);
}

__global__ __launch_bounds__(256, 2)
void swa_h16_kernel(const float* __restrict__ gq, const float* __restrict__ gk,
                    const float* __restrict__ gv, float* __restrict__ gout)
{
    extern __shared__ uint32_t smu[];
    uint32_t* KsU = smu + K_OFF;
    uint32_t* VtU = smu + VT_OFF;
    uint32_t* QPU = smu + P_OFF;       // Q first (transient), then P per tile

    const int tid   = threadIdx.x;
    const int warp  = tid >> 5;
    const int lane  = tid & 31;
    const int group = lane >> 2;       // 0..7 (row within m16 half / n within n8)
    const int qp    = lane & 3;        // 0..3

    const int q0 = blockIdx.x * BQ;
    const int h  = blockIdx.y;

    const float* qh = gq + (size_t)h * SEQ * HD;
    const float* kh = gk + (size_t)h * SEQ * HD;
    const float* vh = gv + (size_t)h * SEQ * HD;
    float*       oh = gout + (size_t)h * SEQ * HD;

    const int r0  = warp * 16 + group;
    const int r1  = r0 + 8;
    const int qi0 = q0 + r0;
    const int qi1 = q0 + r1;

    // ---- stage Q tile into (aliased) smem as f16 pairs ----
    for (int idx = tid; idx < BQ * 16; idx += 256) {
        const int row = idx >> 4, c = (idx & 15) * 4;   // 4 floats
        float4 t = *(const float4*)(qh + (size_t)(q0 + row) * HD + c);
        QPU[row * ROWW + (c >> 1)]     = pack_f16x2(t.x, t.y);
        QPU[row * ROWW + (c >> 1) + 1] = pack_f16x2(t.z, t.w);
    }
    __syncthreads();

    // ---- hoist Q fragments for all 4 k-chunks (16 regs, reused every tile) ----
    uint32_t qf[4][4];
    #pragma unroll
    for (int kc = 0; kc < 4; kc++) {
        const int w0 = kc * 8 + qp;          // u32-word: d = 16*kc + 2*qp
        qf[kc][0] = QPU[r0 * ROWW + w0];
        qf[kc][1] = QPU[r1 * ROWW + w0];
        qf[kc][2] = QPU[r0 * ROWW + w0 + 4]; // d + 8
        qf[kc][3] = QPU[r1 * ROWW + w0 + 4];
    }

    float oacc[8][4];
    #pragma unroll
    for (int nt = 0; nt < 8; nt++)
        #pragma unroll
        for (int j = 0; j < 4; j++) oacc[nt][j] = 0.f;
    float mi0 = -1e30f, mi1 = -1e30f, li0 = 0.f, li1 = 0.f;

    const int kstart = (q0 - WHALF) > 0 ? (q0 - WHALF) : 0;
    const int kend   = (q0 + BQ + WHALF) < SEQ ? (q0 + BQ + WHALF) : SEQ;

    for (int k0 = kstart; k0 < kend; k0 += BK) {
        __syncthreads();   // prior tile's consumers done (Ks/Vt); Q frags read

        // ---- stage K tile (row-major, f16 pairs along d) ----
        for (int idx = tid; idx < BK * 16; idx += 256) {
            const int row = idx >> 4, c = (idx & 15) * 4;
            float4 t = *(const float4*)(kh + (size_t)(k0 + row) * HD + c);
            KsU[row * ROWW + (c >> 1)]     = pack_f16x2(t.x, t.y);
            KsU[row * ROWW + (c >> 1) + 1] = pack_f16x2(t.z, t.w);
        }
        // ---- stage V transposed: Vt[d][kv], f16 pairs along kv ----
        for (int idx = tid; idx < 32 * 16; idx += 256) {
            const int rp = idx >> 4, c = (idx & 15) * 4;   // kv pair rp, d cols c..c+3
            const int r = 2 * rp;
            float4 a = *(const float4*)(vh + (size_t)(k0 + r) * HD + c);
            float4 b = *(const float4*)(vh + (size_t)(k0 + r + 1) * HD + c);
            VtU[(c + 0) * ROWW + rp] = pack_f16x2(a.x, b.x);
            VtU[(c + 1) * ROWW + rp] = pack_f16x2(a.y, b.y);
            VtU[(c + 2) * ROWW + rp] = pack_f16x2(a.z, b.z);
            VtU[(c + 3) * ROWW + rp] = pack_f16x2(a.w, b.w);
        }
        __syncthreads();

        // ---- S = Q K^T : 4 k16-chunks x 8 kv-tiles ----
        float sacc[8][4];
        #pragma unroll
        for (int nt = 0; nt < 8; nt++)
            #pragma unroll
            for (int j = 0; j < 4; j++) sacc[nt][j] = 0.f;

        #pragma unroll
        for (int kc = 0; kc < 4; kc++) {
            const int w0 = kc * 8 + qp;
            #pragma unroll
            for (int nt = 0; nt < 8; nt++) {
                const int kv = nt * 8 + group;
                uint32_t b0 = KsU[kv * ROWW + w0];
                uint32_t b1 = KsU[kv * ROWW + w0 + 4];
                mma_f16(sacc[nt], qf[kc], b0, b1);
            }
        }

        // ---- masked row max ----
        float m0 = -1e30f, m1 = -1e30f;
        #pragma unroll
        for (int nt = 0; nt < 8; nt++) {
            const int kj = k0 + nt * 8 + 2 * qp;
            float x;
            x = sacc[nt][0] * SCALE; if (in_band(qi0, kj)     && x > m0) m0 = x;
            x = sacc[nt][1] * SCALE; if (in_band(qi0, kj + 1) && x > m0) m0 = x;
            x = sacc[nt][2] * SCALE; if (in_band(qi1, kj)     && x > m1) m1 = x;
            x = sacc[nt][3] * SCALE; if (in_band(qi1, kj + 1) && x > m1) m1 = x;
        }
        m0 = fmaxf(m0, __shfl_xor_sync(0xffffffffu, m0, 1));
        m0 = fmaxf(m0, __shfl_xor_sync(0xffffffffu, m0, 2));
        m1 = fmaxf(m1, __shfl_xor_sync(0xffffffffu, m1, 1));
        m1 = fmaxf(m1, __shfl_xor_sync(0xffffffffu, m1, 2));

        const float mn0 = fmaxf(mi0, m0), mn1 = fmaxf(mi1, m1);
        const float al0 = __expf(mi0 - mn0), al1 = __expf(mi1 - mn1);
        mi0 = mn0; mi1 = mn1;

        // ---- exp + mask, P -> warp-private smem rows (f16 pairs) ----
        float rs0 = 0.f, rs1 = 0.f;
        #pragma unroll
        for (int nt = 0; nt < 8; nt++) {
            const int kj = k0 + nt * 8 + 2 * qp;
            const float p00 = in_band(qi0, kj)     ? __expf(sacc[nt][0] * SCALE - mn0) : 0.f;
            const float p01 = in_band(qi0, kj + 1) ? __expf(sacc[nt][1] * SCALE - mn0) : 0.f;
            const float p10 = in_band(qi1, kj)     ? __expf(sacc[nt][2] * SCALE - mn1) : 0.f;
            const float p11 = in_band(qi1, kj + 1) ? __expf(sacc[nt][3] * SCALE - mn1) : 0.f;
            rs0 += p00 + p01;
            rs1 += p10 + p11;
            QPU[r0 * ROWW + nt * 4 + qp] = pack_f16x2(p00, p01);
            QPU[r1 * ROWW + nt * 4 + qp] = pack_f16x2(p10, p11);
        }
        rs0 += __shfl_xor_sync(0xffffffffu, rs0, 1);
        rs0 += __shfl_xor_sync(0xffffffffu, rs0, 2);
        rs1 += __shfl_xor_sync(0xffffffffu, rs1, 1);
        rs1 += __shfl_xor_sync(0xffffffffu, rs1, 2);
        li0 = li0 * al0 + rs0;
        li1 = li1 * al1 + rs1;

        // ---- rescale O ----
        #pragma unroll
        for (int nt = 0; nt < 8; nt++) {
            oacc[nt][0] *= al0; oacc[nt][1] *= al0;
            oacc[nt][2] *= al1; oacc[nt][3] *= al1;
        }
        __syncwarp();   // P exchange is intra-quad within the warp

        // ---- O += P V : 4 kv16-chunks x 8 d-tiles ----
        #pragma unroll
        for (int kc = 0; kc < 4; kc++) {
            const int w0 = kc * 8 + qp;
            uint32_t aP[4];
            aP[0] = QPU[r0 * ROWW + w0];
            aP[1] = QPU[r1 * ROWW + w0];
            aP[2] = QPU[r0 * ROWW + w0 + 4];
            aP[3] = QPU[r1 * ROWW + w0 + 4];
            #pragma unroll
            for (int nt = 0; nt < 8; nt++) {
                const int d = nt * 8 + group;
                uint32_t b0 = VtU[d * ROWW + w0];
                uint32_t b1 = VtU[d * ROWW + w0 + 4];
                mma_f16(oacc[nt], aP, b0, b1);
            }
        }
    }

    // ---- epilogue: normalize, store ----
    const float inv0 = 1.f / li0;
    const float inv1 = 1.f / li1;
    #pragma unroll
    for (int nt = 0; nt < 8; nt++) {
        const int c = nt * 8 + 2 * qp;
        *(float2*)(oh + (size_t)qi0 * HD + c) = make_float2(oacc[nt][0] * inv0, oacc[nt][1] * inv0);
        *(float2*)(oh + (size_t)qi1 * HD + c) = make_float2(oacc[nt][2] * inv1, oacc[nt][3] * inv1);
    }
}

extern "C" void kernel_launch(void* const* d_in, const int* in_sizes, int n_in,
                              void* d_out, int out_size)
{
    const float* q = (const float*)d_in[0];
    const float* k = (const float*)d_in[1];
    const float* v = (const float*)d_in[2];
    float* out = (float*)d_out;
    (void)in_sizes; (void)n_in; (void)out_size;

    cudaFuncSetAttribute(swa_h16_kernel, cudaFuncAttributeMaxDynamicSharedMemorySize,
                         SMEM_BYTES);
    dim3 grid(SEQ / BQ, NH);
    swa_h16_kernel<<<grid, 256, SMEM_BYTES>>>(q, k, v, out);
}